// round 15
// baseline (speedup 1.0000x reference)
#include <cuda_runtime.h>
#include <cuda_fp16.h>
#include <cstdint>

// Problem dims
#define BATCH 256
#define NCOLS 256
#define CH    512
#define NHEAD 8
#define DHEAD 64
#define MROWS (BATCH * NCOLS)   // 65536

// -------- scratch (device globals; allocation is forbidden) --------
__device__ __half g_Xh[(size_t)MROWS * CH];
__device__ __half g_Qh[(size_t)MROWS * CH];
__device__ __half g_Kh[(size_t)MROWS * CH];
__device__ __half g_Vh[(size_t)MROWS * CH];
__device__ __half g_Ah[(size_t)MROWS * CH];
__device__ __half g_Wth[(size_t)3 * CH * CH];   // transposed Wq|Wk|Wv [1536 x 512]
__device__ __half g_WtOh[(size_t)CH * CH];      // transposed Wo [512 x 512]

// ===================== PTX helpers =====================
__device__ __forceinline__ uint32_t smem_u32(const void* p) {
    uint32_t a;
    asm("{ .reg .u64 t; cvta.to.shared.u64 t, %1; cvt.u32.u64 %0, t; }" : "=r"(a) : "l"(p));
    return a;
}
__device__ __forceinline__ void sts16(uint32_t addr, uint16_t v) {
    asm volatile("st.shared.u16 [%0], %1;" :: "r"(addr), "h"(v) : "memory");
}
__device__ __forceinline__ void cpasync16(uint32_t dst, const void* src) {
    asm volatile("cp.async.cg.shared.global [%0], [%1], 16;" :: "r"(dst), "l"(src) : "memory");
}
__device__ __forceinline__ void cp_commit() { asm volatile("cp.async.commit_group;" ::: "memory"); }
template<int N> __device__ __forceinline__ void cp_wait() {
    asm volatile("cp.async.wait_group %0;" :: "n"(N) : "memory");
}
#define LDSM4(r, addr)                                                              \
    asm volatile("ldmatrix.sync.aligned.m8n8.x4.shared.b16 {%0,%1,%2,%3}, [%4];"    \
        : "=r"((r)[0]), "=r"((r)[1]), "=r"((r)[2]), "=r"((r)[3]) : "r"(addr))

#define MMA_F16(d, a, bb0, bb1)                                                     \
    asm volatile("mma.sync.aligned.m16n8k16.row.col.f32.f16.f16.f32 "               \
        "{%0,%1,%2,%3}, {%4,%5,%6,%7}, {%8,%9}, {%0,%1,%2,%3};"                     \
        : "+f"((d)[0]), "+f"((d)[1]), "+f"((d)[2]), "+f"((d)[3])                    \
        : "r"((a)[0]), "r"((a)[1]), "r"((a)[2]), "r"((a)[3]), "r"(bb0), "r"(bb1))

// ===================== merged prep: 4 weight transposes + x conversion =====================
// grid (16,16,68), block (32,8).  z<4: transpose matrix z.  z>=4: conv chunk.
__global__ void prep_kernel(const float* __restrict__ x,
                            const float* __restrict__ Wq, const float* __restrict__ Wk,
                            const float* __restrict__ Wv, const float* __restrict__ Wo,
                            __half* __restrict__ Xh,
                            __half* __restrict__ Wt3, __half* __restrict__ WtO) {
    const int z = blockIdx.z;
    const int tx = threadIdx.x, ty = threadIdx.y;
    if (z < 4) {
        __shared__ float t[32][33];
        const float* W = (z == 0) ? Wq : (z == 1) ? Wk : (z == 2) ? Wv : Wo;
        __half* Wt = (z < 3) ? (Wt3 + (size_t)z * CH * CH) : WtO;
        const int bx = blockIdx.x * 32, by = blockIdx.y * 32;
        #pragma unroll
        for (int j = 0; j < 32; j += 8)
            t[ty + j][tx] = W[(size_t)(by + ty + j) * CH + bx + tx];
        __syncthreads();
        #pragma unroll
        for (int j = 0; j < 32; j += 8)
            Wt[(size_t)(bx + ty + j) * CH + by + tx] = __float2half_rn(t[tx][ty + j]);
    } else {
        const int cb = (z - 4) * 256 + blockIdx.y * 16 + blockIdx.x;   // 0..16383
        const int tid = ty * 32 + tx;
        const size_t i = (size_t)cb * 256 + tid;
        float4 a = ((const float4*)x)[2 * i];
        float4 b = ((const float4*)x)[2 * i + 1];
        __half2 h[4];
        h[0] = __floats2half2_rn(a.x, a.y);
        h[1] = __floats2half2_rn(a.z, a.w);
        h[2] = __floats2half2_rn(b.x, b.y);
        h[3] = __floats2half2_rn(b.z, b.w);
        ((uint2*)Xh)[2 * i]     = make_uint2(*(uint32_t*)&h[0], *(uint32_t*)&h[1]);
        ((uint2*)Xh)[2 * i + 1] = make_uint2(*(uint32_t*)&h[2], *(uint32_t*)&h[3]);
    }
}

// ===================== fp16 mma.sync GEMM: deep pipeline (GS=6, K32 stages) =====================
// C tile [128 x 128] per CTA, 256 threads, 8 warps (2M x 4N), warp tile 64x32.
// 2 CTAs/SM. Stage: A 128x32h (8KB) + B 128x32h (8KB) = 16KB; GS=6 -> 96KB.
// cp_wait<4> keeps ~4 stages of prefetch headroom (vs 1.5 in the GS=3/K64 shape).
// 64B rows of 4x16B units, swizzle u' = u ^ ((row>>1)&3)  (R8-proven).
#define GS 6
#define STAGE_BYTES 16384
#define GEMM_SMEM (GS * STAGE_BYTES)
#define NKSTEP 16

template<typename OutT>
__global__ __launch_bounds__(256, 2) void gemm_f16(
    const __half* __restrict__ A, const __half* __restrict__ Wt,
    const float* __restrict__ b0, const float* __restrict__ b1, const float* __restrict__ b2,
    OutT* __restrict__ o0, OutT* __restrict__ o1, OutT* __restrict__ o2)
{
    extern __shared__ char gsm[];
    const uint32_t sbase = smem_u32(gsm);

    const int tid = threadIdx.x;
    const int lane = tid & 31;
    const int wid = tid >> 5;
    const int warpM = wid & 1;       // 0..1 (64-row strip)
    const int warpN = wid >> 1;      // 0..3 (32-col strip)

    const int mat = blockIdx.x >> 2;
    const int colbase = (blockIdx.x & 3) * 128;
    const float* bias = (mat == 0) ? b0 : (mat == 1) ? b1 : b2;
    OutT* outp = (mat == 0) ? o0 : (mat == 1) ? o1 : o2;

    // ---- cp.async staging: thread -> row r0 (0..127), units u0,u0+1 ----
    const int r0 = tid >> 1;
    const int u0 = (tid & 1) << 1;
    const uint32_t key0 = (uint32_t)((r0 >> 1) & 3);
    const uint32_t aoff0 = (uint32_t)(r0 * 64) + (uint32_t)(((uint32_t)u0 ^ key0) << 4);
    const uint32_t aoff1 = (uint32_t)(r0 * 64) + (uint32_t)((((uint32_t)u0 + 1u) ^ key0) << 4);
    const __half* Ag = A + ((size_t)blockIdx.y * 128 + r0) * CH + u0 * 8;
    const __half* Bg = Wt + ((size_t)blockIdx.x * 128 + r0) * CH + u0 * 8;

    // ---- ldmatrix addressing (64B rows) ----
    const int l15 = lane & 15;
    const int lu = lane >> 4;                // 0/1
    const int key = (l15 >> 1) & 3;
    const uint32_t aBase = (uint32_t)((warpM * 64 + l15) * 64);
    const uint32_t bBase = 8192u + (uint32_t)((warpN * 32 + l15) * 64);
    uint32_t cu[2];
    #pragma unroll
    for (int s = 0; s < 2; s++)
        cu[s] = (uint32_t)(((s * 2 + lu) ^ key) << 4);

    float acc[4][4][4];
    #pragma unroll
    for (int i = 0; i < 4; i++)
        #pragma unroll
        for (int j = 0; j < 4; j++)
            #pragma unroll
            for (int k = 0; k < 4; k++) acc[i][j][k] = 0.0f;

    auto load_stage = [&](int i) {
        const uint32_t stg = sbase + (uint32_t)((i % GS) * STAGE_BYTES);
        const int ko = i * 32;   // halves
        cpasync16(stg + aoff0, Ag + ko);
        cpasync16(stg + aoff1, Ag + ko + 8);
        cpasync16(stg + 8192 + aoff0, Bg + ko);
        cpasync16(stg + 8192 + aoff1, Bg + ko + 8);
        cp_commit();
    };

    load_stage(0);
    load_stage(1);
    load_stage(2);
    load_stage(3);
    load_stage(4);

    #pragma unroll 1
    for (int i = 0; i < NKSTEP; i++) {
        cp_wait<GS - 2>();
        __syncthreads();
        if (i + GS - 1 < NKSTEP) load_stage(i + GS - 1);

        const uint32_t stg = sbase + (uint32_t)((i % GS) * STAGE_BYTES);
        #pragma unroll
        for (int s = 0; s < 2; s++) {
            uint32_t aF[4][4], bF[2][4];
            #pragma unroll
            for (int mt = 0; mt < 4; mt++)
                LDSM4(aF[mt], stg + aBase + (uint32_t)(mt * 1024) + cu[s]);
            #pragma unroll
            for (int p = 0; p < 2; p++)
                LDSM4(bF[p], stg + bBase + (uint32_t)(p * 1024) + cu[s]);
            #pragma unroll
            for (int mt = 0; mt < 4; mt++)
                #pragma unroll
                for (int nt = 0; nt < 4; nt++) {
                    const int p = nt >> 1;
                    if (nt & 1) { MMA_F16(acc[mt][nt], aF[mt], bF[p][1], bF[p][3]); }
                    else        { MMA_F16(acc[mt][nt], aF[mt], bF[p][0], bF[p][2]); }
                }
        }
    }

    // ---- epilogue ----
    const int g = lane >> 2, t = lane & 3;
    #pragma unroll
    for (int mt = 0; mt < 4; mt++) {
        const int row0 = blockIdx.y * 128 + warpM * 64 + mt * 16 + g;
        #pragma unroll
        for (int nt = 0; nt < 4; nt++) {
            const int col = colbase + warpN * 32 + nt * 8 + t * 2;
            const float bv0 = __ldg(&bias[col]);
            const float bv1 = __ldg(&bias[col + 1]);
            if constexpr (sizeof(OutT) == 2) {
                __half2 h0 = __floats2half2_rn(acc[mt][nt][0] + bv0, acc[mt][nt][1] + bv1);
                __half2 h1 = __floats2half2_rn(acc[mt][nt][2] + bv0, acc[mt][nt][3] + bv1);
                *(__half2*)((__half*)outp + (size_t)row0 * CH + col) = h0;
                *(__half2*)((__half*)outp + (size_t)(row0 + 8) * CH + col) = h1;
            } else {
                *(float2*)((float*)outp + (size_t)row0 * CH + col) =
                    make_float2(acc[mt][nt][0] + bv0, acc[mt][nt][1] + bv1);
                *(float2*)((float*)outp + (size_t)(row0 + 8) * CH + col) =
                    make_float2(acc[mt][nt][2] + bv0, acc[mt][nt][3] + bv1);
            }
        }
    }
}

// ===================== fp16 tensor-core causal attention (R10 exact) =====================
#define ATT_SMEM 98304

__global__ __launch_bounds__(256, 2) void attn_f16(
    const __half* __restrict__ Q, const __half* __restrict__ K,
    const __half* __restrict__ V, __half* __restrict__ O)
{
    extern __shared__ char smem[];
    const uint32_t sb = smem_u32(smem);
    const uint32_t qb = sb;
    const uint32_t kb = sb + 32768;
    const uint32_t vb = sb + 65536;

    const int tid = threadIdx.x;
    const int lane = tid & 31;
    const int wid = tid >> 5;

    const int b = blockIdx.x >> 3;
    const int h = blockIdx.x & 7;
    const size_t headOff = (size_t)b * NCOLS * CH + (size_t)h * DHEAD;

    {
        const int u = tid & 7;
        const int r0 = tid >> 3;   // 0..31
        #pragma unroll
        for (int j = 0; j < 8; j++) {
            const int row = r0 + 32 * j;
            const uint32_t soff = (uint32_t)(row * 128) + (uint32_t)((u ^ (row & 7)) << 4);
            cpasync16(qb + soff, Q + headOff + (size_t)row * CH + u * 8);
            cpasync16(kb + soff, K + headOff + (size_t)row * CH + u * 8);
        }
        cp_commit();
    }
    {
        const int keyr = tid;
        const __half* Vr = V + headOff + (size_t)keyr * CH;
        const uint32_t ub = (uint32_t)(keyr >> 3);
        const uint32_t cb = (uint32_t)((keyr & 7) * 2);
        #pragma unroll
        for (int u8 = 0; u8 < 8; u8++) {
            uint4 raw = *(const uint4*)(Vr + u8 * 8);
            const uint16_t* hv = (const uint16_t*)&raw;
            #pragma unroll
            for (int i2 = 0; i2 < 8; i2++) {
                const int d = u8 * 8 + i2;
                const uint32_t phys = (ub & ~7u) | ((ub & 7u) ^ (uint32_t)(d & 7));
                sts16(vb + (uint32_t)(d * 512) + phys * 16 + cb, hv[i2]);
            }
        }
    }
    cp_wait<0>();
    __syncthreads();

    const int l15 = lane & 15;
    const int lu = lane >> 4;
    const int l3 = lane & 7;
    const int g = lane >> 2, t = lane & 3;

    #pragma unroll 1
    for (int pass = 0; pass < 2; pass++) {
        const int s = pass ? (15 - wid) : wid;

        uint32_t qF[4][4];
        #pragma unroll
        for (int k16 = 0; k16 < 4; k16++) {
            const uint32_t phys = (uint32_t)(((k16 * 2 + lu) ^ l3) << 4);
            LDSM4(qF[k16], qb + (uint32_t)((s * 16 + l15) * 128) + phys);
        }

        float o[8][4];
        #pragma unroll
        for (int i = 0; i < 8; i++)
            #pragma unroll
            for (int e = 0; e < 4; e++) o[i][e] = 0.0f;
        float l0 = 0.0f, l1 = 0.0f;

        #pragma unroll 1
        for (int j = 0; j <= s; j++) {
            float sc[2][4];
            #pragma unroll
            for (int nt = 0; nt < 2; nt++)
                #pragma unroll
                for (int e = 0; e < 4; e++) sc[nt][e] = 0.0f;
            #pragma unroll
            for (int k16 = 0; k16 < 4; k16++) {
                const uint32_t phys = (uint32_t)(((k16 * 2 + lu) ^ l3) << 4);
                uint32_t kF[4];
                LDSM4(kF, kb + (uint32_t)((j * 16 + l15) * 128) + phys);
                MMA_F16(sc[0], qF[k16], kF[0], kF[2]);
                MMA_F16(sc[1], qF[k16], kF[1], kF[3]);
            }
            float p[2][4];
            const bool diag = (j == s);
            #pragma unroll
            for (int nt = 0; nt < 2; nt++) {
                const int col = nt * 8 + 2 * t;
                #pragma unroll
                for (int e = 0; e < 4; e++) {
                    const int cc = col + (e & 1);
                    const int rr = (e < 2) ? g : (g + 8);
                    const bool keep = !diag || (cc <= rr);
                    p[nt][e] = keep ? __expf(sc[nt][e] * 0.125f) : 0.0f;
                }
            }
            __half2 h0 = __floats2half2_rn(p[0][0], p[0][1]);
            __half2 h1 = __floats2half2_rn(p[0][2], p[0][3]);
            __half2 h2 = __floats2half2_rn(p[1][0], p[1][1]);
            __half2 h3 = __floats2half2_rn(p[1][2], p[1][3]);
            {
                float2 f;
                f = __half22float2(h0); l0 += f.x + f.y;
                f = __half22float2(h2); l0 += f.x + f.y;
                f = __half22float2(h1); l1 += f.x + f.y;
                f = __half22float2(h3); l1 += f.x + f.y;
            }
            uint32_t aP[4];
            aP[0] = *(uint32_t*)&h0; aP[1] = *(uint32_t*)&h1;
            aP[2] = *(uint32_t*)&h2; aP[3] = *(uint32_t*)&h3;
            const uint32_t uj = (uint32_t)(j * 2) + (uint32_t)lu;
            const uint32_t physv = ((uj & ~7u) | ((uj & 7u) ^ (uint32_t)l3)) << 4;
            #pragma unroll
            for (int p4 = 0; p4 < 4; p4++) {
                uint32_t vF[4];
                LDSM4(vF, vb + (uint32_t)((p4 * 16 + l15) * 512) + physv);
                MMA_F16(o[2 * p4],     aP, vF[0], vF[2]);
                MMA_F16(o[2 * p4 + 1], aP, vF[1], vF[3]);
            }
        }

        l0 += __shfl_xor_sync(0xFFFFFFFFu, l0, 1);
        l0 += __shfl_xor_sync(0xFFFFFFFFu, l0, 2);
        l1 += __shfl_xor_sync(0xFFFFFFFFu, l1, 1);
        l1 += __shfl_xor_sync(0xFFFFFFFFu, l1, 2);
        const float inv0 = 1.0f / l0;
        const float inv1 = 1.0f / l1;

        const int row0 = s * 16 + g;
        __half* Ob0 = (__half*)(O + headOff + (size_t)row0 * CH);
        __half* Ob1 = (__half*)(O + headOff + (size_t)(row0 + 8) * CH);
        #pragma unroll
        for (int nt = 0; nt < 8; nt++) {
            const int col = nt * 8 + 2 * t;
            *(__half2*)(Ob0 + col) = __floats2half2_rn(o[nt][0] * inv0, o[nt][1] * inv0);
            *(__half2*)(Ob1 + col) = __floats2half2_rn(o[nt][2] * inv1, o[nt][3] * inv1);
        }
    }
}

// ===================== launch =====================
extern "C" void kernel_launch(void* const* d_in, const int* in_sizes, int n_in,
                              void* d_out, int out_size)
{
    const float* x  = (const float*)d_in[0];
    const float* Wq = (const float*)d_in[1];
    const float* bq = (const float*)d_in[2];
    const float* Wk = (const float*)d_in[3];
    const float* bk = (const float*)d_in[4];
    const float* Wv = (const float*)d_in[5];
    const float* bv = (const float*)d_in[6];
    const float* Wo = (const float*)d_in[7];
    const float* bo = (const float*)d_in[8];
    float* out = (float*)d_out;

    __half *pXh, *pQh, *pKh, *pVh, *pAh, *pWth, *pWtOh;
    cudaGetSymbolAddress((void**)&pXh, g_Xh);
    cudaGetSymbolAddress((void**)&pQh, g_Qh);
    cudaGetSymbolAddress((void**)&pKh, g_Kh);
    cudaGetSymbolAddress((void**)&pVh, g_Vh);
    cudaGetSymbolAddress((void**)&pAh, g_Ah);
    cudaGetSymbolAddress((void**)&pWth, g_Wth);
    cudaGetSymbolAddress((void**)&pWtOh, g_WtOh);

    cudaFuncSetAttribute(gemm_f16<__half>, cudaFuncAttributeMaxDynamicSharedMemorySize, GEMM_SMEM);
    cudaFuncSetAttribute(gemm_f16<float>, cudaFuncAttributeMaxDynamicSharedMemorySize, GEMM_SMEM);
    cudaFuncSetAttribute(attn_f16, cudaFuncAttributeMaxDynamicSharedMemorySize, ATT_SMEM);

    // merged prep: 4 transposes (z<4) + x->half conversion (z>=4)
    prep_kernel<<<dim3(16, 16, 68), dim3(32, 8)>>>(x, Wq, Wk, Wv, Wo, pXh, pWth, pWtOh);

    // QKV fused: blockIdx.x 0..11 -> (Q|K|V) x 4 col-tiles of 128; M-tiles of 128
    gemm_f16<__half><<<dim3(12, 512), 256, GEMM_SMEM>>>(pXh, pWth, bq, bk, bv, pQh, pKh, pVh);

    attn_f16<<<BATCH * NHEAD, 256, ATT_SMEM>>>(pQh, pKh, pVh, pAh);

    // output projection (fp32 out + bias)
    gemm_f16<float><<<dim3(4, 512), 256, GEMM_SMEM>>>(pAh, pWtOh, bo, bo, bo, out, out, out);
}

// round 16
// speedup vs baseline: 1.2236x; 1.2236x over previous
#include <cuda_runtime.h>
#include <cuda_fp16.h>
#include <cstdint>

// Problem dims
#define BATCH 256
#define NCOLS 256
#define CH    512
#define NHEAD 8
#define DHEAD 64
#define MROWS (BATCH * NCOLS)   // 65536

// -------- scratch (device globals; allocation is forbidden) --------
__device__ __half g_Xh[(size_t)MROWS * CH];
__device__ __half g_Qh[(size_t)MROWS * CH];
__device__ __half g_Kh[(size_t)MROWS * CH];
__device__ __half g_Vh[(size_t)MROWS * CH];
__device__ __half g_Ah[(size_t)MROWS * CH];
__device__ __half g_Wth[(size_t)3 * CH * CH];   // transposed Wq|Wk|Wv [1536 x 512]
__device__ __half g_WtOh[(size_t)CH * CH];      // transposed Wo [512 x 512]

// ===================== PTX helpers =====================
__device__ __forceinline__ uint32_t smem_u32(const void* p) {
    uint32_t a;
    asm("{ .reg .u64 t; cvta.to.shared.u64 t, %1; cvt.u32.u64 %0, t; }" : "=r"(a) : "l"(p));
    return a;
}
__device__ __forceinline__ void sts16(uint32_t addr, uint16_t v) {
    asm volatile("st.shared.u16 [%0], %1;" :: "r"(addr), "h"(v) : "memory");
}
__device__ __forceinline__ void cpasync16(uint32_t dst, const void* src) {
    asm volatile("cp.async.cg.shared.global [%0], [%1], 16;" :: "r"(dst), "l"(src) : "memory");
}
__device__ __forceinline__ void cp_commit() { asm volatile("cp.async.commit_group;" ::: "memory"); }
template<int N> __device__ __forceinline__ void cp_wait() {
    asm volatile("cp.async.wait_group %0;" :: "n"(N) : "memory");
}
#define LDSM4(r, addr)                                                              \
    asm volatile("ldmatrix.sync.aligned.m8n8.x4.shared.b16 {%0,%1,%2,%3}, [%4];"    \
        : "=r"((r)[0]), "=r"((r)[1]), "=r"((r)[2]), "=r"((r)[3]) : "r"(addr))

#define MMA_F16(d, a, bb0, bb1)                                                     \
    asm volatile("mma.sync.aligned.m16n8k16.row.col.f32.f16.f16.f32 "               \
        "{%0,%1,%2,%3}, {%4,%5,%6,%7}, {%8,%9}, {%0,%1,%2,%3};"                     \
        : "+f"((d)[0]), "+f"((d)[1]), "+f"((d)[2]), "+f"((d)[3])                    \
        : "r"((a)[0]), "r"((a)[1]), "r"((a)[2]), "r"((a)[3]), "r"(bb0), "r"(bb1))

// ===================== merged prep: 4 weight transposes + x conversion =====================
// grid (16,16,68), block (32,8).  z<4: transpose matrix z.  z>=4: conv chunk.
__global__ void prep_kernel(const float* __restrict__ x,
                            const float* __restrict__ Wq, const float* __restrict__ Wk,
                            const float* __restrict__ Wv, const float* __restrict__ Wo,
                            __half* __restrict__ Xh,
                            __half* __restrict__ Wt3, __half* __restrict__ WtO) {
    const int z = blockIdx.z;
    const int tx = threadIdx.x, ty = threadIdx.y;
    if (z < 4) {
        __shared__ float t[32][33];
        const float* W = (z == 0) ? Wq : (z == 1) ? Wk : (z == 2) ? Wv : Wo;
        __half* Wt = (z < 3) ? (Wt3 + (size_t)z * CH * CH) : WtO;
        const int bx = blockIdx.x * 32, by = blockIdx.y * 32;
        #pragma unroll
        for (int j = 0; j < 32; j += 8)
            t[ty + j][tx] = W[(size_t)(by + ty + j) * CH + bx + tx];
        __syncthreads();
        #pragma unroll
        for (int j = 0; j < 32; j += 8)
            Wt[(size_t)(bx + ty + j) * CH + by + tx] = __float2half_rn(t[tx][ty + j]);
    } else {
        const int cb = (z - 4) * 256 + blockIdx.y * 16 + blockIdx.x;   // 0..16383
        const int tid = ty * 32 + tx;
        const size_t i = (size_t)cb * 256 + tid;
        float4 a = ((const float4*)x)[2 * i];
        float4 b = ((const float4*)x)[2 * i + 1];
        __half2 h[4];
        h[0] = __floats2half2_rn(a.x, a.y);
        h[1] = __floats2half2_rn(a.z, a.w);
        h[2] = __floats2half2_rn(b.x, b.y);
        h[3] = __floats2half2_rn(b.z, b.w);
        ((uint2*)Xh)[2 * i]     = make_uint2(*(uint32_t*)&h[0], *(uint32_t*)&h[1]);
        ((uint2*)Xh)[2 * i + 1] = make_uint2(*(uint32_t*)&h[2], *(uint32_t*)&h[3]);
    }
}

// ===================== fp16 mma.sync GEMM (R10 proven: 128x128, 8 warps, K64) =====================
#define GS 3
#define STAGE_BYTES 32768
#define GEMM_SMEM (GS * STAGE_BYTES)
#define NKSTEP 8

template<typename OutT>
__global__ __launch_bounds__(256, 2) void gemm_f16(
    const __half* __restrict__ A, const __half* __restrict__ Wt,
    const float* __restrict__ b0, const float* __restrict__ b1, const float* __restrict__ b2,
    OutT* __restrict__ o0, OutT* __restrict__ o1, OutT* __restrict__ o2)
{
    extern __shared__ char gsm[];
    const uint32_t sbase = smem_u32(gsm);

    const int tid = threadIdx.x;
    const int lane = tid & 31;
    const int wid = tid >> 5;
    const int warpM = wid & 1;       // 0..1 (64-row strip)
    const int warpN = wid >> 1;      // 0..3 (32-col strip)

    const int mat = blockIdx.x >> 2;
    const int colbase = (blockIdx.x & 3) * 128;
    const float* bias = (mat == 0) ? b0 : (mat == 1) ? b1 : b2;
    OutT* outp = (mat == 0) ? o0 : (mat == 1) ? o1 : o2;

    // ---- cp.async staging: rows r0+32j (j=0..3), unit u0; 4 A + 4 B per thread ----
    const int r0 = tid >> 3;                 // 0..31
    const int u0 = tid & 7;
    const uint32_t swzA = (uint32_t)((u0 ^ (r0 & 7)) << 4);
    const __half* Ag = A + ((size_t)blockIdx.y * 128 + r0) * CH + u0 * 8;
    const __half* Bg = Wt + ((size_t)blockIdx.x * 128 + r0) * CH + u0 * 8;
    const uint32_t aoff = (uint32_t)(r0 * 128) + swzA;

    // ---- ldmatrix addressing: 128B rows, unit for sub-step s = (s*2+lu) ^ l3 ----
    const int l15 = lane & 15;
    const int lu = lane >> 4;                // 0/1
    const int l3 = lane & 7;
    const uint32_t aBase = (uint32_t)((warpM * 64 + l15) * 128);
    const uint32_t bBase = 16384u + (uint32_t)((warpN * 32 + l15) * 128);
    uint32_t cu[4];
    #pragma unroll
    for (int s = 0; s < 4; s++)
        cu[s] = (uint32_t)(((s * 2 + lu) ^ l3) << 4);

    float acc[4][4][4];
    #pragma unroll
    for (int i = 0; i < 4; i++)
        #pragma unroll
        for (int j = 0; j < 4; j++)
            #pragma unroll
            for (int k = 0; k < 4; k++) acc[i][j][k] = 0.0f;

    auto load_stage = [&](int i) {
        const uint32_t stg = sbase + (uint32_t)((i % GS) * STAGE_BYTES);
        const int ko = i * 64;   // halves
        #pragma unroll
        for (int j = 0; j < 4; j++) {
            cpasync16(stg + aoff + (uint32_t)(j * 4096), Ag + ko + (size_t)(32 * j) * CH);
            cpasync16(stg + 16384 + aoff + (uint32_t)(j * 4096), Bg + ko + (size_t)(32 * j) * CH);
        }
        cp_commit();
    };

    load_stage(0);
    load_stage(1);

    #pragma unroll 1
    for (int i = 0; i < NKSTEP; i++) {
        cp_wait<GS - 2>();
        __syncthreads();
        if (i + GS - 1 < NKSTEP) load_stage(i + GS - 1);

        const uint32_t stg = sbase + (uint32_t)((i % GS) * STAGE_BYTES);
        #pragma unroll
        for (int s = 0; s < 4; s++) {
            uint32_t aF[4][4], bF[2][4];
            #pragma unroll
            for (int mt = 0; mt < 4; mt++)
                LDSM4(aF[mt], stg + aBase + (uint32_t)(mt * 2048) + cu[s]);
            #pragma unroll
            for (int p = 0; p < 2; p++)
                LDSM4(bF[p], stg + bBase + (uint32_t)(p * 2048) + cu[s]);
            #pragma unroll
            for (int mt = 0; mt < 4; mt++)
                #pragma unroll
                for (int nt = 0; nt < 4; nt++) {
                    const int p = nt >> 1;
                    if (nt & 1) { MMA_F16(acc[mt][nt], aF[mt], bF[p][1], bF[p][3]); }
                    else        { MMA_F16(acc[mt][nt], aF[mt], bF[p][0], bF[p][2]); }
                }
        }
    }

    // ---- epilogue ----
    const int g = lane >> 2, t = lane & 3;
    #pragma unroll
    for (int mt = 0; mt < 4; mt++) {
        const int row0 = blockIdx.y * 128 + warpM * 64 + mt * 16 + g;
        #pragma unroll
        for (int nt = 0; nt < 4; nt++) {
            const int col = colbase + warpN * 32 + nt * 8 + t * 2;
            const float bv0 = __ldg(&bias[col]);
            const float bv1 = __ldg(&bias[col + 1]);
            if constexpr (sizeof(OutT) == 2) {
                __half2 h0 = __floats2half2_rn(acc[mt][nt][0] + bv0, acc[mt][nt][1] + bv1);
                __half2 h1 = __floats2half2_rn(acc[mt][nt][2] + bv0, acc[mt][nt][3] + bv1);
                *(__half2*)((__half*)outp + (size_t)row0 * CH + col) = h0;
                *(__half2*)((__half*)outp + (size_t)(row0 + 8) * CH + col) = h1;
            } else {
                *(float2*)((float*)outp + (size_t)row0 * CH + col) =
                    make_float2(acc[mt][nt][0] + bv0, acc[mt][nt][1] + bv1);
                *(float2*)((float*)outp + (size_t)(row0 + 8) * CH + col) =
                    make_float2(acc[mt][nt][2] + bv0, acc[mt][nt][3] + bv1);
            }
        }
    }
}

// ===================== fp16 tensor-core causal attention (R10 exact) =====================
#define ATT_SMEM 98304

__global__ __launch_bounds__(256, 2) void attn_f16(
    const __half* __restrict__ Q, const __half* __restrict__ K,
    const __half* __restrict__ V, __half* __restrict__ O)
{
    extern __shared__ char smem[];
    const uint32_t sb = smem_u32(smem);
    const uint32_t qb = sb;
    const uint32_t kb = sb + 32768;
    const uint32_t vb = sb + 65536;

    const int tid = threadIdx.x;
    const int lane = tid & 31;
    const int wid = tid >> 5;

    const int b = blockIdx.x >> 3;
    const int h = blockIdx.x & 7;
    const size_t headOff = (size_t)b * NCOLS * CH + (size_t)h * DHEAD;

    {
        const int u = tid & 7;
        const int r0 = tid >> 3;   // 0..31
        #pragma unroll
        for (int j = 0; j < 8; j++) {
            const int row = r0 + 32 * j;
            const uint32_t soff = (uint32_t)(row * 128) + (uint32_t)((u ^ (row & 7)) << 4);
            cpasync16(qb + soff, Q + headOff + (size_t)row * CH + u * 8);
            cpasync16(kb + soff, K + headOff + (size_t)row * CH + u * 8);
        }
        cp_commit();
    }
    {
        const int keyr = tid;
        const __half* Vr = V + headOff + (size_t)keyr * CH;
        const uint32_t ub = (uint32_t)(keyr >> 3);
        const uint32_t cb = (uint32_t)((keyr & 7) * 2);
        #pragma unroll
        for (int u8 = 0; u8 < 8; u8++) {
            uint4 raw = *(const uint4*)(Vr + u8 * 8);
            const uint16_t* hv = (const uint16_t*)&raw;
            #pragma unroll
            for (int i2 = 0; i2 < 8; i2++) {
                const int d = u8 * 8 + i2;
                const uint32_t phys = (ub & ~7u) | ((ub & 7u) ^ (uint32_t)(d & 7));
                sts16(vb + (uint32_t)(d * 512) + phys * 16 + cb, hv[i2]);
            }
        }
    }
    cp_wait<0>();
    __syncthreads();

    const int l15 = lane & 15;
    const int lu = lane >> 4;
    const int l3 = lane & 7;
    const int g = lane >> 2, t = lane & 3;

    #pragma unroll 1
    for (int pass = 0; pass < 2; pass++) {
        const int s = pass ? (15 - wid) : wid;

        uint32_t qF[4][4];
        #pragma unroll
        for (int k16 = 0; k16 < 4; k16++) {
            const uint32_t phys = (uint32_t)(((k16 * 2 + lu) ^ l3) << 4);
            LDSM4(qF[k16], qb + (uint32_t)((s * 16 + l15) * 128) + phys);
        }

        float o[8][4];
        #pragma unroll
        for (int i = 0; i < 8; i++)
            #pragma unroll
            for (int e = 0; e < 4; e++) o[i][e] = 0.0f;
        float l0 = 0.0f, l1 = 0.0f;

        #pragma unroll 1
        for (int j = 0; j <= s; j++) {
            float sc[2][4];
            #pragma unroll
            for (int nt = 0; nt < 2; nt++)
                #pragma unroll
                for (int e = 0; e < 4; e++) sc[nt][e] = 0.0f;
            #pragma unroll
            for (int k16 = 0; k16 < 4; k16++) {
                const uint32_t phys = (uint32_t)(((k16 * 2 + lu) ^ l3) << 4);
                uint32_t kF[4];
                LDSM4(kF, kb + (uint32_t)((j * 16 + l15) * 128) + phys);
                MMA_F16(sc[0], qF[k16], kF[0], kF[2]);
                MMA_F16(sc[1], qF[k16], kF[1], kF[3]);
            }
            float p[2][4];
            const bool diag = (j == s);
            #pragma unroll
            for (int nt = 0; nt < 2; nt++) {
                const int col = nt * 8 + 2 * t;
                #pragma unroll
                for (int e = 0; e < 4; e++) {
                    const int cc = col + (e & 1);
                    const int rr = (e < 2) ? g : (g + 8);
                    const bool keep = !diag || (cc <= rr);
                    p[nt][e] = keep ? __expf(sc[nt][e] * 0.125f) : 0.0f;
                }
            }
            __half2 h0 = __floats2half2_rn(p[0][0], p[0][1]);
            __half2 h1 = __floats2half2_rn(p[0][2], p[0][3]);
            __half2 h2 = __floats2half2_rn(p[1][0], p[1][1]);
            __half2 h3 = __floats2half2_rn(p[1][2], p[1][3]);
            {
                float2 f;
                f = __half22float2(h0); l0 += f.x + f.y;
                f = __half22float2(h2); l0 += f.x + f.y;
                f = __half22float2(h1); l1 += f.x + f.y;
                f = __half22float2(h3); l1 += f.x + f.y;
            }
            uint32_t aP[4];
            aP[0] = *(uint32_t*)&h0; aP[1] = *(uint32_t*)&h1;
            aP[2] = *(uint32_t*)&h2; aP[3] = *(uint32_t*)&h3;
            const uint32_t uj = (uint32_t)(j * 2) + (uint32_t)lu;
            const uint32_t physv = ((uj & ~7u) | ((uj & 7u) ^ (uint32_t)l3)) << 4;
            #pragma unroll
            for (int p4 = 0; p4 < 4; p4++) {
                uint32_t vF[4];
                LDSM4(vF, vb + (uint32_t)((p4 * 16 + l15) * 512) + physv);
                MMA_F16(o[2 * p4],     aP, vF[0], vF[2]);
                MMA_F16(o[2 * p4 + 1], aP, vF[1], vF[3]);
            }
        }

        l0 += __shfl_xor_sync(0xFFFFFFFFu, l0, 1);
        l0 += __shfl_xor_sync(0xFFFFFFFFu, l0, 2);
        l1 += __shfl_xor_sync(0xFFFFFFFFu, l1, 1);
        l1 += __shfl_xor_sync(0xFFFFFFFFu, l1, 2);
        const float inv0 = 1.0f / l0;
        const float inv1 = 1.0f / l1;

        const int row0 = s * 16 + g;
        __half* Ob0 = (__half*)(O + headOff + (size_t)row0 * CH);
        __half* Ob1 = (__half*)(O + headOff + (size_t)(row0 + 8) * CH);
        #pragma unroll
        for (int nt = 0; nt < 8; nt++) {
            const int col = nt * 8 + 2 * t;
            *(__half2*)(Ob0 + col) = __floats2half2_rn(o[nt][0] * inv0, o[nt][1] * inv0);
            *(__half2*)(Ob1 + col) = __floats2half2_rn(o[nt][2] * inv1, o[nt][3] * inv1);
        }
    }
}

// ===================== launch =====================
extern "C" void kernel_launch(void* const* d_in, const int* in_sizes, int n_in,
                              void* d_out, int out_size)
{
    const float* x  = (const float*)d_in[0];
    const float* Wq = (const float*)d_in[1];
    const float* bq = (const float*)d_in[2];
    const float* Wk = (const float*)d_in[3];
    const float* bk = (const float*)d_in[4];
    const float* Wv = (const float*)d_in[5];
    const float* bv = (const float*)d_in[6];
    const float* Wo = (const float*)d_in[7];
    const float* bo = (const float*)d_in[8];
    float* out = (float*)d_out;

    __half *pXh, *pQh, *pKh, *pVh, *pAh, *pWth, *pWtOh;
    cudaGetSymbolAddress((void**)&pXh, g_Xh);
    cudaGetSymbolAddress((void**)&pQh, g_Qh);
    cudaGetSymbolAddress((void**)&pKh, g_Kh);
    cudaGetSymbolAddress((void**)&pVh, g_Vh);
    cudaGetSymbolAddress((void**)&pAh, g_Ah);
    cudaGetSymbolAddress((void**)&pWth, g_Wth);
    cudaGetSymbolAddress((void**)&pWtOh, g_WtOh);

    cudaFuncSetAttribute(gemm_f16<__half>, cudaFuncAttributeMaxDynamicSharedMemorySize, GEMM_SMEM);
    cudaFuncSetAttribute(gemm_f16<float>, cudaFuncAttributeMaxDynamicSharedMemorySize, GEMM_SMEM);
    cudaFuncSetAttribute(attn_f16, cudaFuncAttributeMaxDynamicSharedMemorySize, ATT_SMEM);

    // merged prep: 4 transposes (z<4) + x->half conversion (z>=4)
    prep_kernel<<<dim3(16, 16, 68), dim3(32, 8)>>>(x, Wq, Wk, Wv, Wo, pXh, pWth, pWtOh);

    // QKV fused: blockIdx.x 0..11 -> (Q|K|V) x 4 col-tiles of 128; M-tiles of 128
    gemm_f16<__half><<<dim3(12, 512), 256, GEMM_SMEM>>>(pXh, pWth, bq, bk, bv, pQh, pKh, pVh);

    attn_f16<<<BATCH * NHEAD, 256, ATT_SMEM>>>(pQh, pKh, pVh, pAh);

    // output projection (fp32 out + bias)
    gemm_f16<float><<<dim3(4, 512), 256, GEMM_SMEM>>>(pAh, pWtOh, bo, bo, bo, out, out, out);
}